// round 1
// baseline (speedup 1.0000x reference)
#include <cuda_runtime.h>

#define T  1024
#define HD 2048
#define ID 4096
#define E  8

#define BM 128
#define BN 64
#define BK 16
#define APAD 132   // As row pitch in floats (528B, 16B-aligned, kills STS conflicts)
#define BPAD 68    // Bs row pitch in floats (272B, 16B-aligned)

// ---- scratch (static device globals: allocation-free per harness rules) ----
__device__ float g_h_shared[(size_t)T * ID];
__device__ float g_h_routed[(size_t)T * ID];
__device__ int   g_expert[T];
__device__ float g_score[T];
__device__ int   g_perm[T];
__device__ int   g_offsets[E + 1];

// ============================================================================
// Router: one warp per token. logits = x @ w_router [H,E]; argmax (first-max
// tie-break, matching jax.lax.top_k k=1); score = sigmoid(max logit).
// ============================================================================
__global__ void router_kernel(const float* __restrict__ x,
                              const float* __restrict__ wr) {
    int warp = (blockIdx.x * blockDim.x + threadIdx.x) >> 5;
    int lane = threadIdx.x & 31;
    if (warp >= T) return;
    const float* xr = x + (size_t)warp * HD;
    float acc[E];
#pragma unroll
    for (int e = 0; e < E; e++) acc[e] = 0.f;
    for (int h = lane; h < HD; h += 32) {
        float xv = xr[h];
        const float* w = wr + (size_t)h * E;
#pragma unroll
        for (int e = 0; e < E; e++) acc[e] += xv * w[e];
    }
#pragma unroll
    for (int e = 0; e < E; e++) {
#pragma unroll
        for (int o = 16; o; o >>= 1) acc[e] += __shfl_xor_sync(0xffffffffu, acc[e], o);
    }
    if (lane == 0) {
        int best = 0; float bv = acc[0];
#pragma unroll
        for (int e = 1; e < E; e++) if (acc[e] > bv) { bv = acc[e]; best = e; }
        g_expert[warp] = best;
        g_score[warp]  = 1.f / (1.f + __expf(-bv));
    }
}

// ============================================================================
// Histogram + exclusive scan + permutation (single block, T threads).
// Intra-expert order is atomic-dependent but the final output is invariant to
// it (each row computed independently, scattered back by token id).
// ============================================================================
__global__ void perm_kernel() {
    __shared__ int cnt[E];
    __shared__ int off[E + 1];
    __shared__ int cur[E];
    int t = threadIdx.x;
    if (t < E) cnt[t] = 0;
    __syncthreads();
    int e = g_expert[t];
    atomicAdd(&cnt[e], 1);
    __syncthreads();
    if (t == 0) {
        off[0] = 0;
        for (int i = 0; i < E; i++) off[i + 1] = off[i] + cnt[i];
    }
    __syncthreads();
    if (t < E) cur[t] = off[t];
    __syncthreads();
    int pos = atomicAdd(&cur[e], 1);
    g_perm[pos] = t;
    if (t <= E) g_offsets[t] = off[t];
}

// ============================================================================
// GEMM1: fused gate+up.  h = silu(Xs@Wg) * (Xs@Wu).
//   routed=0: X rows 0..T-1, scale 1, weights ws_*, out g_h_shared
//   routed=1: expert = blockIdx.z, rows gathered via g_perm, scale = score,
//             weights we_*[e], out g_h_routed (permuted order, contiguous)
// Tile 128x64x16, 256 threads, 8x4 outputs/thread, dual accumulators.
// ============================================================================
__global__ __launch_bounds__(256, 2)
void gateup_kernel(const float* __restrict__ X,
                   const float* __restrict__ Wg,
                   const float* __restrict__ Wu,
                   int routed) {
    __shared__ float As [BK][APAD];
    __shared__ float Bgs[BK][BPAD];
    __shared__ float Bus[BK][BPAD];
    __shared__ int   s_tok[BM];
    __shared__ float s_scl[BM];

    int tid = threadIdx.x;
    int rowBase, cnt;
    const float *wg, *wu;
    float* Hout;
    if (routed) {
        int e   = blockIdx.z;
        rowBase = g_offsets[e];
        cnt     = g_offsets[e + 1] - rowBase;
        wg      = Wg + (size_t)e * HD * ID;
        wu      = Wu + (size_t)e * HD * ID;
        Hout    = g_h_routed;
    } else {
        rowBase = 0; cnt = T; wg = Wg; wu = Wu; Hout = g_h_shared;
    }
    int m0 = blockIdx.y * BM;
    if (m0 >= cnt) return;
    int n0 = blockIdx.x * BN;

    if (tid < BM) {
        int gr = m0 + tid;
        int tok = 0; float sc = 0.f;
        if (gr < cnt) {
            if (routed) { tok = g_perm[rowBase + gr]; sc = g_score[tok]; }
            else        { tok = gr;                   sc = 1.f; }
        }
        s_tok[tid] = tok; s_scl[tid] = sc;
    }
    __syncthreads();

    int mt = tid >> 4;           // 0..15 -> rows mt*8 .. mt*8+7
    int nt = tid & 15;           // 0..15 -> cols nt*4 .. nt*4+3
    float accg[8][4], accu[8][4];
#pragma unroll
    for (int j = 0; j < 8; j++)
#pragma unroll
        for (int i = 0; i < 4; i++) { accg[j][i] = 0.f; accu[j][i] = 0.f; }

    int ac = tid >> 6;           // k-chunk 0..3
    int ar = tid & 63;           // row base 0..63
    int bk = tid >> 4;           // 0..15
    int bn = (tid & 15) << 2;    // 0..60

    for (int kt = 0; kt < HD; kt += BK) {
        // stage A (transpose into [k][m], scale folded in; sc==0 rows -> zeros)
#pragma unroll
        for (int half = 0; half < 2; half++) {
            int r = ar + 64 * half;
            float sc = s_scl[r];
            float4 v = make_float4(0.f, 0.f, 0.f, 0.f);
            if (sc != 0.f) {
                v = *(const float4*)(X + (size_t)s_tok[r] * HD + kt + ac * 4);
                v.x *= sc; v.y *= sc; v.z *= sc; v.w *= sc;
            }
            As[ac * 4 + 0][r] = v.x;
            As[ac * 4 + 1][r] = v.y;
            As[ac * 4 + 2][r] = v.z;
            As[ac * 4 + 3][r] = v.w;
        }
        // stage B (gate + up)
        {
            float4 vg = *(const float4*)(wg + (size_t)(kt + bk) * ID + n0 + bn);
            float4 vu = *(const float4*)(wu + (size_t)(kt + bk) * ID + n0 + bn);
            *(float4*)&Bgs[bk][bn] = vg;
            *(float4*)&Bus[bk][bn] = vu;
        }
        __syncthreads();

#pragma unroll
        for (int k = 0; k < BK; k++) {
            float4 a0 = *(const float4*)&As[k][mt * 8];
            float4 a1 = *(const float4*)&As[k][mt * 8 + 4];
            float4 bg = *(const float4*)&Bgs[k][nt * 4];
            float4 bu = *(const float4*)&Bus[k][nt * 4];
            float av[8]  = {a0.x, a0.y, a0.z, a0.w, a1.x, a1.y, a1.z, a1.w};
            float bgv[4] = {bg.x, bg.y, bg.z, bg.w};
            float buv[4] = {bu.x, bu.y, bu.z, bu.w};
#pragma unroll
            for (int j = 0; j < 8; j++)
#pragma unroll
                for (int i = 0; i < 4; i++) {
                    accg[j][i] = fmaf(av[j], bgv[i], accg[j][i]);
                    accu[j][i] = fmaf(av[j], buv[i], accu[j][i]);
                }
        }
        __syncthreads();
    }

    // epilogue: h = silu(g) * u
#pragma unroll
    for (int j = 0; j < 8; j++) {
        int gr = m0 + mt * 8 + j;
        if (gr < cnt) {
            float o[4];
#pragma unroll
            for (int i = 0; i < 4; i++) {
                float g = accg[j][i];
                o[i] = (g / (1.f + __expf(-g))) * accu[j][i];
            }
            *(float4*)&Hout[(size_t)(rowBase + gr) * ID + n0 + nt * 4] =
                make_float4(o[0], o[1], o[2], o[3]);
        }
    }
}

// ============================================================================
// GEMM2: down projection.
//   routed=0: out[t] = h_shared[t] @ ws_down            (writes all of out)
//   routed=1: out[perm[p]] += h_routed[p] @ we_down[e]  (runs after shared)
// ============================================================================
__global__ __launch_bounds__(256, 2)
void down_kernel(const float* __restrict__ Wd,
                 float* __restrict__ out,
                 int routed) {
    __shared__ float As[BK][APAD];
    __shared__ float Bs[BK][BPAD];

    int tid = threadIdx.x;
    int rowBase, cnt;
    const float* wd;
    const float* Hin;
    if (routed) {
        int e   = blockIdx.z;
        rowBase = g_offsets[e];
        cnt     = g_offsets[e + 1] - rowBase;
        wd      = Wd + (size_t)e * ID * HD;
        Hin     = g_h_routed;
    } else {
        rowBase = 0; cnt = T; wd = Wd; Hin = g_h_shared;
    }
    int m0 = blockIdx.y * BM;
    if (m0 >= cnt) return;
    int n0 = blockIdx.x * BN;

    int mt = tid >> 4;
    int nt = tid & 15;
    float acc[8][4];
#pragma unroll
    for (int j = 0; j < 8; j++)
#pragma unroll
        for (int i = 0; i < 4; i++) acc[j][i] = 0.f;

    int ac = tid >> 6;
    int ar = tid & 63;
    int bk = tid >> 4;
    int bn = (tid & 15) << 2;

    for (int kt = 0; kt < ID; kt += BK) {
#pragma unroll
        for (int half = 0; half < 2; half++) {
            int r  = ar + 64 * half;
            int gr = m0 + r;
            float4 v = make_float4(0.f, 0.f, 0.f, 0.f);
            if (gr < cnt)
                v = *(const float4*)&Hin[(size_t)(rowBase + gr) * ID + kt + ac * 4];
            As[ac * 4 + 0][r] = v.x;
            As[ac * 4 + 1][r] = v.y;
            As[ac * 4 + 2][r] = v.z;
            As[ac * 4 + 3][r] = v.w;
        }
        {
            float4 vb = *(const float4*)(wd + (size_t)(kt + bk) * HD + n0 + bn);
            *(float4*)&Bs[bk][bn] = vb;
        }
        __syncthreads();

#pragma unroll
        for (int k = 0; k < BK; k++) {
            float4 a0 = *(const float4*)&As[k][mt * 8];
            float4 a1 = *(const float4*)&As[k][mt * 8 + 4];
            float4 b  = *(const float4*)&Bs[k][nt * 4];
            float av[8] = {a0.x, a0.y, a0.z, a0.w, a1.x, a1.y, a1.z, a1.w};
            float bv[4] = {b.x, b.y, b.z, b.w};
#pragma unroll
            for (int j = 0; j < 8; j++)
#pragma unroll
                for (int i = 0; i < 4; i++)
                    acc[j][i] = fmaf(av[j], bv[i], acc[j][i]);
        }
        __syncthreads();
    }

#pragma unroll
    for (int j = 0; j < 8; j++) {
        int gr = m0 + mt * 8 + j;
        if (gr < cnt) {
            int token = routed ? g_perm[rowBase + gr] : gr;
            float* po = out + (size_t)token * HD + n0 + nt * 4;
            float4 o = make_float4(acc[j][0], acc[j][1], acc[j][2], acc[j][3]);
            if (routed) {
                float4 prev = *(float4*)po;
                o.x += prev.x; o.y += prev.y; o.z += prev.z; o.w += prev.w;
            }
            *(float4*)po = o;
        }
    }
}

// ============================================================================
extern "C" void kernel_launch(void* const* d_in, const int* in_sizes, int n_in,
                              void* d_out, int out_size) {
    const float* x        = (const float*)d_in[0];
    const float* w_router = (const float*)d_in[1];
    const float* ws_gate  = (const float*)d_in[2];
    const float* ws_up    = (const float*)d_in[3];
    const float* ws_down  = (const float*)d_in[4];
    const float* we_gate  = (const float*)d_in[5];
    const float* we_up    = (const float*)d_in[6];
    const float* we_down  = (const float*)d_in[7];
    float* out = (float*)d_out;

    (void)in_sizes; (void)n_in; (void)out_size;

    router_kernel<<<T / 8, 256>>>(x, w_router);
    perm_kernel<<<1, T>>>();

    // gate+up, shared then routed (independent outputs, stream-ordered anyway)
    dim3 g1s(ID / BN, T / BM, 1);
    gateup_kernel<<<g1s, 256>>>(x, ws_gate, ws_up, 0);
    dim3 g1r(ID / BN, T / BM, E);
    gateup_kernel<<<g1r, 256>>>(x, we_gate, we_up, 1);

    // down: shared pass WRITES every element of out, routed pass then +=
    dim3 g2s(HD / BN, T / BM, 1);
    down_kernel<<<g2s, 256>>>(ws_down, out, 0);
    dim3 g2r(HD / BN, T / BM, E);
    down_kernel<<<g2r, 256>>>(we_down, out, 1);
}

// round 2
// speedup vs baseline: 1.1450x; 1.1450x over previous
#include <cuda_runtime.h>
#include <cuda_bf16.h>
#include <mma.h>
using namespace nvcuda;

#define T  1024
#define HD 2048
#define ID 4096
#define E  8

#define BM 128
#define BN 64
#define BK 32
#define APITCH 40   // bf16 elements; 80B row, multiple of 16B
#define BPITCH 72   // bf16 elements; 144B row, multiple of 16B
#define CPITCH 68   // f32 elements; 272B row, multiple of 16B

// ---- scratch (static device globals; allocation-free per harness rules) ----
__device__ float g_h_shared[(size_t)T * ID];
__device__ float g_h_routed[(size_t)(T + E * BM) * ID];  // per-expert 128-row pad
__device__ int   g_expert[T];
__device__ float g_score[T];
__device__ int   g_perm[T];
__device__ int   g_offsets[E + 1];

__device__ __forceinline__ void split_bf16(float v, __nv_bfloat16& h, __nv_bfloat16& l) {
    h = __float2bfloat16_rn(v);
    l = __float2bfloat16_rn(v - __bfloat162float(h));
}

// ============================================================================
// Router: one warp per token; argmax (first-max tie-break) + sigmoid score.
// ============================================================================
__global__ void router_kernel(const float* __restrict__ x,
                              const float* __restrict__ wr) {
    int warp = (blockIdx.x * blockDim.x + threadIdx.x) >> 5;
    int lane = threadIdx.x & 31;
    if (warp >= T) return;
    const float* xr = x + (size_t)warp * HD;
    float acc[E];
#pragma unroll
    for (int e = 0; e < E; e++) acc[e] = 0.f;
    for (int h = lane; h < HD; h += 32) {
        float xv = xr[h];
        const float* w = wr + (size_t)h * E;
#pragma unroll
        for (int e = 0; e < E; e++) acc[e] += xv * w[e];
    }
#pragma unroll
    for (int e = 0; e < E; e++) {
#pragma unroll
        for (int o = 16; o; o >>= 1) acc[e] += __shfl_xor_sync(0xffffffffu, acc[e], o);
    }
    if (lane == 0) {
        int best = 0; float bv = acc[0];
#pragma unroll
        for (int e = 1; e < E; e++) if (acc[e] > bv) { bv = acc[e]; best = e; }
        g_expert[warp] = best;
        g_score[warp]  = 1.f / (1.f + __expf(-bv));
    }
}

// ============================================================================
// Histogram + scan + permutation (single block). Output is invariant to the
// atomic-dependent intra-expert order (rows scattered back by token id).
// ============================================================================
__global__ void perm_kernel() {
    __shared__ int cnt[E];
    __shared__ int off[E + 1];
    __shared__ int cur[E];
    int t = threadIdx.x;
    if (t < E) cnt[t] = 0;
    __syncthreads();
    int e = g_expert[t];
    atomicAdd(&cnt[e], 1);
    __syncthreads();
    if (t == 0) {
        off[0] = 0;
        for (int i = 0; i < E; i++) off[i + 1] = off[i] + cnt[i];
    }
    __syncthreads();
    if (t < E) cur[t] = off[t];
    __syncthreads();
    int pos = atomicAdd(&cur[e], 1);
    g_perm[pos] = t;
    if (t <= E) g_offsets[t] = off[t];
}

// ============================================================================
// GEMM1 (wmma, split-bf16): h = silu(Xs@Wg) * (Xs@Wu)
// Block tile 128x64xK, 8 warps (4x2), warp tile 32x32 for each of gate/up.
// Split into hi/lo bf16 during global->smem staging; 3 MMAs per product.
// Routed scratch rows use per-expert padded base; pad rows are exact zeros.
// ============================================================================
__global__ __launch_bounds__(256)
void gateup_kernel(const float* __restrict__ X,
                   const float* __restrict__ Wg,
                   const float* __restrict__ Wu,
                   int routed) {
    __shared__ __nv_bfloat16 Ah[BM][APITCH], Al[BM][APITCH];
    __shared__ __nv_bfloat16 Bgh[BK][BPITCH], Bgl[BK][BPITCH];
    __shared__ __nv_bfloat16 Buh[BK][BPITCH], Bul[BK][BPITCH];
    __shared__ int   s_tok[BM];
    __shared__ float s_scl[BM];

    int tid = threadIdx.x;
    int obase, cnt, pbase;
    const float *wg, *wu;
    float* Hout;
    if (routed) {
        int e = blockIdx.z;
        obase = g_offsets[e];
        cnt   = g_offsets[e + 1] - obase;
        pbase = obase + e * BM;
        wg = Wg + (size_t)e * HD * ID;
        wu = Wu + (size_t)e * HD * ID;
        Hout = g_h_routed;
    } else {
        obase = 0; cnt = T; pbase = 0; wg = Wg; wu = Wu; Hout = g_h_shared;
    }
    int m0 = blockIdx.y * BM;
    if (m0 >= cnt) return;
    int n0 = blockIdx.x * BN;

    if (tid < BM) {
        int gr = m0 + tid;
        int tok = 0; float sc = 0.f;
        if (gr < cnt) {
            if (routed) { tok = g_perm[obase + gr]; sc = g_score[tok]; }
            else        { tok = gr;                 sc = 1.f; }
        }
        s_tok[tid] = tok; s_scl[tid] = sc;
    }
    __syncthreads();

    int warp = tid >> 5;
    int wm0 = (warp >> 1) * 32;
    int wn0 = (warp & 1) * 32;

    wmma::fragment<wmma::accumulator, 16, 16, 16, float> accg[2][2], accu[2][2];
#pragma unroll
    for (int mi = 0; mi < 2; mi++)
#pragma unroll
        for (int ni = 0; ni < 2; ni++) {
            wmma::fill_fragment(accg[mi][ni], 0.f);
            wmma::fill_fragment(accu[mi][ni], 0.f);
        }

    int ar = tid & 127;          // A row
    int ak = (tid >> 7) * 16;    // A k-base (0 or 16)

    for (int kt = 0; kt < HD; kt += BK) {
        // ---- stage A (gather + scale + split) ----
        {
            float sc = s_scl[ar];
            const float* xp = X + (size_t)s_tok[ar] * HD + kt + ak;
#pragma unroll
            for (int i = 0; i < 4; i++) {
                float4 v = make_float4(0.f, 0.f, 0.f, 0.f);
                if (sc != 0.f) {
                    v = *(const float4*)(xp + i * 4);
                    v.x *= sc; v.y *= sc; v.z *= sc; v.w *= sc;
                }
                int c = ak + i * 4;
                split_bf16(v.x, Ah[ar][c + 0], Al[ar][c + 0]);
                split_bf16(v.y, Ah[ar][c + 1], Al[ar][c + 1]);
                split_bf16(v.z, Ah[ar][c + 2], Al[ar][c + 2]);
                split_bf16(v.w, Ah[ar][c + 3], Al[ar][c + 3]);
            }
        }
        // ---- stage B (gate + up, split) ----
#pragma unroll
        for (int i = 0; i < 2; i++) {
            int idx = tid * 2 + i;        // 0..511
            int kr  = idx >> 4;           // 0..31
            int c4  = (idx & 15) * 4;     // 0..60
            float4 vg = *(const float4*)(wg + (size_t)(kt + kr) * ID + n0 + c4);
            float4 vu = *(const float4*)(wu + (size_t)(kt + kr) * ID + n0 + c4);
            split_bf16(vg.x, Bgh[kr][c4 + 0], Bgl[kr][c4 + 0]);
            split_bf16(vg.y, Bgh[kr][c4 + 1], Bgl[kr][c4 + 1]);
            split_bf16(vg.z, Bgh[kr][c4 + 2], Bgl[kr][c4 + 2]);
            split_bf16(vg.w, Bgh[kr][c4 + 3], Bgl[kr][c4 + 3]);
            split_bf16(vu.x, Buh[kr][c4 + 0], Bul[kr][c4 + 0]);
            split_bf16(vu.y, Buh[kr][c4 + 1], Bul[kr][c4 + 1]);
            split_bf16(vu.z, Buh[kr][c4 + 2], Bul[kr][c4 + 2]);
            split_bf16(vu.w, Buh[kr][c4 + 3], Bul[kr][c4 + 3]);
        }
        __syncthreads();

#pragma unroll
        for (int kk = 0; kk < BK; kk += 16) {
            wmma::fragment<wmma::matrix_a, 16, 16, 16, __nv_bfloat16, wmma::row_major> ah[2], al[2];
#pragma unroll
            for (int mi = 0; mi < 2; mi++) {
                wmma::load_matrix_sync(ah[mi], &Ah[wm0 + mi * 16][kk], APITCH);
                wmma::load_matrix_sync(al[mi], &Al[wm0 + mi * 16][kk], APITCH);
            }
            wmma::fragment<wmma::matrix_b, 16, 16, 16, __nv_bfloat16, wmma::row_major> bgh[2], bgl[2], buh[2], bul[2];
#pragma unroll
            for (int ni = 0; ni < 2; ni++) {
                wmma::load_matrix_sync(bgh[ni], &Bgh[kk][wn0 + ni * 16], BPITCH);
                wmma::load_matrix_sync(bgl[ni], &Bgl[kk][wn0 + ni * 16], BPITCH);
                wmma::load_matrix_sync(buh[ni], &Buh[kk][wn0 + ni * 16], BPITCH);
                wmma::load_matrix_sync(bul[ni], &Bul[kk][wn0 + ni * 16], BPITCH);
            }
#pragma unroll
            for (int mi = 0; mi < 2; mi++)
#pragma unroll
                for (int ni = 0; ni < 2; ni++) {
                    wmma::mma_sync(accg[mi][ni], ah[mi], bgh[ni], accg[mi][ni]);
                    wmma::mma_sync(accg[mi][ni], ah[mi], bgl[ni], accg[mi][ni]);
                    wmma::mma_sync(accg[mi][ni], al[mi], bgh[ni], accg[mi][ni]);
                    wmma::mma_sync(accu[mi][ni], ah[mi], buh[ni], accu[mi][ni]);
                    wmma::mma_sync(accu[mi][ni], ah[mi], bul[ni], accu[mi][ni]);
                    wmma::mma_sync(accu[mi][ni], al[mi], buh[ni], accu[mi][ni]);
                }
        }
        __syncthreads();
    }

    // epilogue: h = silu(g) * u, written as full tiles (pad rows are zeros)
#pragma unroll
    for (int mi = 0; mi < 2; mi++)
#pragma unroll
        for (int ni = 0; ni < 2; ni++) {
            wmma::fragment<wmma::accumulator, 16, 16, 16, float> hf;
#pragma unroll
            for (int i = 0; i < hf.num_elements; i++) {
                float g = accg[mi][ni].x[i];
                hf.x[i] = (g / (1.f + __expf(-g))) * accu[mi][ni].x[i];
            }
            wmma::store_matrix_sync(
                Hout + (size_t)(pbase + m0 + wm0 + mi * 16) * ID + n0 + wn0 + ni * 16,
                hf, ID, wmma::mem_row_major);
        }
}

// ============================================================================
// GEMM2 (wmma, split-bf16): down projection with smem-staged scatter epilogue.
//   routed=0: out[t]        = h_shared[t] @ ws_down     (writes all of out)
//   routed=1: out[perm[p]] += h_routed[p] @ we_down[e]  (after shared pass)
// ============================================================================
__global__ __launch_bounds__(256)
void down_kernel(const float* __restrict__ Wd,
                 float* __restrict__ out,
                 int routed) {
    // overlay: [A hi/lo bf16 | B hi/lo bf16] during mainloop, C f32 in epilogue
    __shared__ __align__(16) char smem_raw[BM * CPITCH * 4];  // 34816 B (largest)
    __nv_bfloat16* Ah = (__nv_bfloat16*)smem_raw;             // [BM][APITCH]
    __nv_bfloat16* Al = Ah + BM * APITCH;
    __nv_bfloat16* Bh = Al + BM * APITCH;                     // [BK][BPITCH]
    __nv_bfloat16* Bl = Bh + BK * BPITCH;
    float* Cs = (float*)smem_raw;                             // [BM][CPITCH]

    int tid = threadIdx.x;
    int obase, cnt, pbase;
    const float* wd;
    const float* Hin;
    if (routed) {
        int e = blockIdx.z;
        obase = g_offsets[e];
        cnt   = g_offsets[e + 1] - obase;
        pbase = obase + e * BM;
        wd  = Wd + (size_t)e * ID * HD;
        Hin = g_h_routed;
    } else {
        obase = 0; cnt = T; pbase = 0; wd = Wd; Hin = g_h_shared;
    }
    int m0 = blockIdx.y * BM;
    if (m0 >= cnt) return;
    int n0 = blockIdx.x * BN;

    int warp = tid >> 5;
    int wm0 = (warp >> 1) * 32;
    int wn0 = (warp & 1) * 32;

    wmma::fragment<wmma::accumulator, 16, 16, 16, float> acc[2][2];
#pragma unroll
    for (int mi = 0; mi < 2; mi++)
#pragma unroll
        for (int ni = 0; ni < 2; ni++) wmma::fill_fragment(acc[mi][ni], 0.f);

    int ar = tid & 127;
    int ak = (tid >> 7) * 16;

    for (int kt = 0; kt < ID; kt += BK) {
        // ---- stage A (contiguous scratch rows; pad rows are zeros) ----
        {
            const float* hp = Hin + (size_t)(pbase + m0 + ar) * ID + kt + ak;
#pragma unroll
            for (int i = 0; i < 4; i++) {
                float4 v = *(const float4*)(hp + i * 4);
                int c = ak + i * 4;
                split_bf16(v.x, Ah[ar * APITCH + c + 0], Al[ar * APITCH + c + 0]);
                split_bf16(v.y, Ah[ar * APITCH + c + 1], Al[ar * APITCH + c + 1]);
                split_bf16(v.z, Ah[ar * APITCH + c + 2], Al[ar * APITCH + c + 2]);
                split_bf16(v.w, Ah[ar * APITCH + c + 3], Al[ar * APITCH + c + 3]);
            }
        }
        // ---- stage B ----
#pragma unroll
        for (int i = 0; i < 2; i++) {
            int idx = tid * 2 + i;
            int kr  = idx >> 4;
            int c4  = (idx & 15) * 4;
            float4 vb = *(const float4*)(wd + (size_t)(kt + kr) * HD + n0 + c4);
            split_bf16(vb.x, Bh[kr * BPITCH + c4 + 0], Bl[kr * BPITCH + c4 + 0]);
            split_bf16(vb.y, Bh[kr * BPITCH + c4 + 1], Bl[kr * BPITCH + c4 + 1]);
            split_bf16(vb.z, Bh[kr * BPITCH + c4 + 2], Bl[kr * BPITCH + c4 + 2]);
            split_bf16(vb.w, Bh[kr * BPITCH + c4 + 3], Bl[kr * BPITCH + c4 + 3]);
        }
        __syncthreads();

#pragma unroll
        for (int kk = 0; kk < BK; kk += 16) {
            wmma::fragment<wmma::matrix_a, 16, 16, 16, __nv_bfloat16, wmma::row_major> ah[2], al[2];
#pragma unroll
            for (int mi = 0; mi < 2; mi++) {
                wmma::load_matrix_sync(ah[mi], Ah + (wm0 + mi * 16) * APITCH + kk, APITCH);
                wmma::load_matrix_sync(al[mi], Al + (wm0 + mi * 16) * APITCH + kk, APITCH);
            }
            wmma::fragment<wmma::matrix_b, 16, 16, 16, __nv_bfloat16, wmma::row_major> bh[2], bl[2];
#pragma unroll
            for (int ni = 0; ni < 2; ni++) {
                wmma::load_matrix_sync(bh[ni], Bh + kk * BPITCH + wn0 + ni * 16, BPITCH);
                wmma::load_matrix_sync(bl[ni], Bl + kk * BPITCH + wn0 + ni * 16, BPITCH);
            }
#pragma unroll
            for (int mi = 0; mi < 2; mi++)
#pragma unroll
                for (int ni = 0; ni < 2; ni++) {
                    wmma::mma_sync(acc[mi][ni], ah[mi], bh[ni], acc[mi][ni]);
                    wmma::mma_sync(acc[mi][ni], ah[mi], bl[ni], acc[mi][ni]);
                    wmma::mma_sync(acc[mi][ni], al[mi], bh[ni], acc[mi][ni]);
                }
        }
        __syncthreads();
    }

    // epilogue: stage to smem, then guarded scatter (+= for routed)
#pragma unroll
    for (int mi = 0; mi < 2; mi++)
#pragma unroll
        for (int ni = 0; ni < 2; ni++)
            wmma::store_matrix_sync(Cs + (wm0 + mi * 16) * CPITCH + wn0 + ni * 16,
                                    acc[mi][ni], CPITCH, wmma::mem_row_major);
    __syncthreads();

#pragma unroll
    for (int it = 0; it < 8; it++) {
        int idx = tid + it * 256;       // 0..2047 float4s
        int row = idx >> 4;
        int c4  = (idx & 15) * 4;
        int gr  = m0 + row;
        if (gr < cnt) {
            int token = routed ? g_perm[obase + gr] : gr;
            float* po = out + (size_t)token * HD + n0 + c4;
            const float* ps = Cs + row * CPITCH + c4;
            float4 o = make_float4(ps[0], ps[1], ps[2], ps[3]);
            if (routed) {
                float4 prev = *(float4*)po;
                o.x += prev.x; o.y += prev.y; o.z += prev.z; o.w += prev.w;
            }
            *(float4*)po = o;
        }
    }
}

// ============================================================================
extern "C" void kernel_launch(void* const* d_in, const int* in_sizes, int n_in,
                              void* d_out, int out_size) {
    const float* x        = (const float*)d_in[0];
    const float* w_router = (const float*)d_in[1];
    const float* ws_gate  = (const float*)d_in[2];
    const float* ws_up    = (const float*)d_in[3];
    const float* ws_down  = (const float*)d_in[4];
    const float* we_gate  = (const float*)d_in[5];
    const float* we_up    = (const float*)d_in[6];
    const float* we_down  = (const float*)d_in[7];
    float* out = (float*)d_out;

    (void)in_sizes; (void)n_in; (void)out_size;

    router_kernel<<<T / 8, 256>>>(x, w_router);
    perm_kernel<<<1, T>>>();

    dim3 g1s(ID / BN, T / BM, 1);
    gateup_kernel<<<g1s, 256>>>(x, ws_gate, ws_up, 0);
    dim3 g1r(ID / BN, T / BM, E);
    gateup_kernel<<<g1r, 256>>>(x, we_gate, we_up, 1);

    dim3 g2s(HD / BN, T / BM, 1);
    down_kernel<<<g2s, 256>>>(ws_down, out, 0);
    dim3 g2r(HD / BN, T / BM, E);
    down_kernel<<<g2r, 256>>>(we_down, out, 1);
}